// round 10
// baseline (speedup 1.0000x reference)
#include <cuda_runtime.h>
#include <cuda_bf16.h>
#include <cstdint>
#include <cstddef>

#define NROWS 8192
#define FD 64
#define CJ 64
#define TILE_I 128
#define JSPLIT 8
#define NCHUNKS 128                // 8192 / 64
#define NCHAIN 16                  // chunks per CTA = 1024 / 64
#define BIMG 18432                 // per-chunk B image: 144 rows x 128 B (U;V)

typedef unsigned long long ull;

__device__ float g_Wh[NROWS * FD];
__device__ float g_s[NROWS], g_d[NROWS];
__device__ float g_es[NROWS], g_fs[NROWS], g_ed[NROWS], g_fd[NROWS];
__device__ uint8_t g_UV[NCHUNKS * BIMG];
__device__ float g_pacc[JSPLIT][NROWS][FD];
__device__ float g_pl[JSPLIT][NROWS];

__device__ __forceinline__ float fast_exp(float t) {
    float x = t * 1.4426950408889634f;
    x = fminf(fmaxf(x, -126.0f), 126.0f);
    float c = x + 12582912.0f;
    int   ic = __float_as_int(c);
    float f  = x - (c - 12582912.0f);
    float y  = f * 0.6931471805599453f;
    float p = 1.3888889e-3f;
    p = fmaf(p, y, 8.3333333e-3f);
    p = fmaf(p, y, 4.1666667e-2f);
    p = fmaf(p, y, 1.6666667e-1f);
    p = fmaf(p, y, 0.5f);
    p = fmaf(p, y, 1.0f);
    p = fmaf(p, y, 1.0f);
    return p * __int_as_float(((ic & 0x7FFFFF) - 0x400000 + 127) << 23);
}

__device__ __forceinline__ uint32_t smem_u32(const void* p) {
    uint32_t a;
    asm("{ .reg .u64 t; cvta.to.shared.u64 t, %1; cvt.u32.u64 %0, t; }"
        : "=r"(a) : "l"(p));
    return a;
}
#define LDSM4(a0, a1, a2, a3, ad)                                              \
    asm volatile("ldmatrix.sync.aligned.m8n8.x4.shared.b16 {%0,%1,%2,%3}, [%4];" \
                 : "=r"(a0), "=r"(a1), "=r"(a2), "=r"(a3) : "r"(ad))
#define LDSM2(b0, b1, ad)                                                      \
    asm volatile("ldmatrix.sync.aligned.m8n8.x2.shared.b16 {%0,%1}, [%2];"     \
                 : "=r"(b0), "=r"(b1) : "r"(ad))
#define MMA16816(d, a0, a1, a2, a3, b0, b1)                                    \
    asm volatile("mma.sync.aligned.m16n8k16.row.col.f32.bf16.bf16.f32 "        \
                 "{%0,%1,%2,%3}, {%4,%5,%6,%7}, {%8,%9}, {%0,%1,%2,%3};"       \
                 : "+f"((d)[0]), "+f"((d)[1]), "+f"((d)[2]), "+f"((d)[3])      \
                 : "r"(a0), "r"(a1), "r"(a2), "r"(a3), "r"(b0), "r"(b1))
#define CP16(dst, src)                                                         \
    asm volatile("cp.async.ca.shared.global [%0], [%1], 16;"                   \
                 :: "r"(dst), "l"(src))
#define CP_COMMIT() asm volatile("cp.async.commit_group;" ::: "memory")
#define CP_WAIT0()  asm volatile("cp.async.wait_group 0;" ::: "memory")

// ---------------------------------------------------------------------------
// K1: Wh = X@W, fused s/d and exp-factor tables
// ---------------------------------------------------------------------------
__global__ __launch_bounds__(128) void k_wh(const float* __restrict__ inp,
                                            const float* __restrict__ W,
                                            const float* __restrict__ a) {
    __shared__ float sIn[8 * 65];
    __shared__ float sW[64 * 64];
    __shared__ float sA[128];
    int tid = threadIdx.x;
    int i0  = blockIdx.x * 8;
    for (int idx = tid; idx < 512; idx += 128) {
        int r = idx >> 6, k = idx & 63;
        sIn[r * 65 + k] = inp[i0 * 64 + idx];
    }
    const float4* W4 = (const float4*)W;
    float4* sW4w = (float4*)sW;
#pragma unroll
    for (int q = 0; q < 8; ++q) sW4w[tid + q * 128] = W4[tid + q * 128];
    if (tid < 128) sA[tid] = a[tid];
    __syncthreads();

    int r = tid >> 4, fg = tid & 15;
    float acc[4];
#pragma unroll
    for (int q = 0; q < 4; ++q) acc[q] = 0.f;
    const float4* sW4 = (const float4*)sW;
#pragma unroll 16
    for (int k = 0; k < 64; ++k) {
        float  x = sIn[r * 65 + k];
        float4 w = sW4[k * 16 + fg];
        acc[0] = fmaf(x, w.x, acc[0]);
        acc[1] = fmaf(x, w.y, acc[1]);
        acc[2] = fmaf(x, w.z, acc[2]);
        acc[3] = fmaf(x, w.w, acc[3]);
    }
    int row = i0 + r;
    float ps = 0.f, pd = 0.f;
#pragma unroll
    for (int q = 0; q < 4; ++q) {
        ps = fmaf(acc[q], sA[fg * 4 + q], ps);
        pd = fmaf(acc[q], sA[64 + fg * 4 + q], pd);
    }
    *(float4*)(g_Wh + row * 64 + fg * 4) =
        make_float4(acc[0], acc[1], acc[2], acc[3]);
#pragma unroll
    for (int o = 1; o < 16; o <<= 1) {
        ps += __shfl_xor_sync(0xffffffffu, ps, o, 16);
        pd += __shfl_xor_sync(0xffffffffu, pd, o, 16);
    }
    if (fg == 0) {
        float sc = fminf(fmaxf(ps, -87.f), 80.f);
        float dc = fminf(fmaxf(pd, -87.f), 80.f);
        g_s[row] = ps; g_d[row] = pd;
        g_es[row] = fast_exp(sc);        g_fs[row] = fast_exp(0.2f * sc);
        g_ed[row] = fast_exp(dc);        g_fd[row] = fast_exp(0.2f * dc);
    }
}

// ---------------------------------------------------------------------------
// K2: prepacked bf16 B images, CJ=64: 144 rows x 128B (U rows 0-71, V 72-143)
// ---------------------------------------------------------------------------
__device__ __forceinline__ uint32_t pk_bf2(float lo, float hi) {
    uint32_t l = (uint32_t)__bfloat16_as_ushort(__float2bfloat16_rn(lo));
    uint32_t h = (uint32_t)__bfloat16_as_ushort(__float2bfloat16_rn(hi));
    return l | (h << 16);
}
__global__ __launch_bounds__(256) void k_prep() {
    int c  = blockIdx.x;
    int jb = c * CJ;
    uint8_t* base = g_UV + (size_t)c * BIMG;
    for (int idx = threadIdx.x; idx < 72 * 32; idx += 256) {
        int n = idx >> 5, jp = idx & 31, j = 2 * jp;
        float e0 = g_ed[jb + j], e1 = g_ed[jb + j + 1];
        float f0 = g_fd[jb + j], f1 = g_fd[jb + j + 1];
        float u0, u1, v0, v1;
        if (n < 64) {
            float w0 = g_Wh[(size_t)(jb + j) * 64 + n];
            float w1 = g_Wh[(size_t)(jb + j + 1) * 64 + n];
            u0 = e0 * w0; u1 = e1 * w1; v0 = f0 * w0; v1 = f1 * w1;
        } else if (n == 64) { u0 = e0; u1 = e1; v0 = f0; v1 = f1; }
        else { u0 = u1 = v0 = v1 = 0.f; }
        uint32_t c16 = (uint32_t)(jp >> 2);
        uint32_t sw  = ((c16 ^ (uint32_t)(n & 7)) << 4) + (jp & 3) * 4;
        *(uint32_t*)(base + n * 128 + sw)         = pk_bf2(u0, u1);
        *(uint32_t*)(base + (72 + n) * 128 + sw)  = pk_bf2(v0, v1);
    }
}

// ---------------------------------------------------------------------------
// K3: cp.async-pipelined adj + exact binary masks + HMMA.
// RACE FIX vs R9: no prefetch on the last iteration, and CP_WAIT0 before the
// epilogue reuses smem (staging sC overlaps the adj buffer region).
// ---------------------------------------------------------------------------
#define SM_S   0
#define SM_ES  512
#define SM_FS  1024
#define SM_A   2048
#define SM_B   (SM_A + 128 * 256)        // 34816
#define SM_ADJ (SM_B + BIMG)             // 53248
#define SM_TOT (SM_ADJ + 128 * 256)      // 86016
#define CPITCH 76

__global__ __launch_bounds__(256, 2) void k_attn(const int* __restrict__ adj) {
    extern __shared__ char smem[];
    float* sS  = (float*)(smem + SM_S);
    float* sES = (float*)(smem + SM_ES);
    float* sFS = (float*)(smem + SM_FS);
    int tid = threadIdx.x, wid = tid >> 5, lane = tid & 31;
    int itile = blockIdx.x & 63, sp = blockIdx.x >> 6;
    int i0 = itile * TILE_I;
    int jbase0 = sp * (NROWS / JSPLIT);
    int rb = wid * 16;

    if (tid < 128) {
        sS[tid]  = g_s[i0 + tid];
        sES[tid] = g_es[i0 + tid];
        sFS[tid] = g_fs[i0 + tid];
    }

    int part = wid >> 2;               // 0: C@U, 1: D@V
    int mrb  = (wid & 3) * 32;

    float acc[72];
#pragma unroll
    for (int q = 0; q < 72; ++q) acc[q] = 0.f;

    uint32_t sAu = smem_u32(smem) + SM_A;
    uint32_t sBu = smem_u32(smem) + SM_B;
    uint32_t sJu = smem_u32(smem) + SM_ADJ;
    uint32_t aRow0 = (uint32_t)mrb + (lane & 15);
    uint32_t aRow1 = aRow0 + 16;
    uint32_t aB0 = sAu + aRow0 * 256;
    uint32_t aB1 = sAu + aRow1 * 256;
    uint32_t cBase = (uint32_t)part * 8 + (uint32_t)(lane >> 4);
    uint32_t bRowL = (uint32_t)(lane & 7);
    uint32_t bHalf = (uint32_t)((lane >> 3) & 1);
    uint32_t bBase = sBu + bRowL * 128 + (uint32_t)part * 72 * 128;

    // cp.async addressing: thread t covers row = t>>1, 8x 16B pieces
    int cpRow = tid >> 1, cpSub = tid & 1;
    const int* cpSrcBase = adj + (size_t)(i0 + cpRow) * NROWS + cpSub * 4;
    uint32_t   cpDst     = sJu + cpRow * 256 + cpSub * 16;

    // prologue: prefetch chunk 0
    {
        const int* src = cpSrcBase + jbase0;
#pragma unroll
        for (int q = 0; q < 8; ++q)
            CP16(cpDst + q * 32, src + q * 8);
        CP_COMMIT();
    }

    int j0 = 2 * lane;

    for (int cc = 0; cc < NCHAIN; ++cc) {
        int gch = sp * NCHAIN + cc;
        int jb  = jbase0 + cc * CJ;
        CP_WAIT0();
        __syncthreads();               // adj(cc) ready; prev MMA done with A/B
        {   // copy prepacked B image (18432 B = 2304 uint2)
            const uint2* src = (const uint2*)(g_UV + (size_t)gch * BIMG);
            uint2* dst = (uint2*)(smem + SM_B);
#pragma unroll
            for (int q = 0; q < 9; ++q) dst[tid + q * 256] = src[tid + q * 256];
        }
        // mask build: 16 rows/warp, 2 j per lane, adj from smem
        float2 dv = *(const float2*)(g_d + jb + j0);
#pragma unroll
        for (int r = 0; r < 16; ++r) {
            uint32_t R = (uint32_t)rb + r;
            int2 a2;
            asm volatile("ld.shared.v2.u32 {%0,%1}, [%2];"
                         : "=r"(a2.x), "=r"(a2.y) : "r"(sJu + R * 256 + lane * 8));
            float sr = sS[R];
            float t0 = sr + dv.x, t1 = sr + dv.y;
            uint32_t h = (t0 > 0.f ? 0x3F80u : 0u) | (t1 > 0.f ? 0x3F800000u : 0u);
            uint32_t m = (uint32_t)a2.x * 0xFFFFu + (uint32_t)a2.y * 0xFFFF0000u;
            uint32_t u = (uint32_t)(lane >> 2) ^ (R & 7);
            uint32_t off = R * 256 + (u << 4) + (lane & 3) * 4;
            *(uint32_t*)(smem + SM_A + off)       = h & m;
            *(uint32_t*)(smem + SM_A + off + 128) = (h ^ 0x3F803F80u) & m;
        }
        __syncthreads();               // A,B ready; adjbuf reads done
        // prefetch adj(cc+1) — streams during MMA. NOT on last iteration:
        // the epilogue reuses smem that overlaps the adj buffer.
        if (cc < NCHAIN - 1) {
            const int* src = cpSrcBase + jbase0 + (cc + 1) * CJ;
#pragma unroll
            for (int q = 0; q < 8; ++q)
                CP16(cpDst + q * 32, src + q * 8);
            CP_COMMIT();
        }

        // HMMA: this warp's part, 32 rows, 9 n-tiles, 4 k-steps
#pragma unroll
        for (int ks = 0; ks < 4; ++ks) {
            uint32_t c16 = cBase + 2 * (uint32_t)ks;
            uint32_t A0, A1, A2, A3, A4, A5, A6, A7;
            LDSM4(A0, A1, A2, A3, aB0 + ((c16 ^ (aRow0 & 7)) << 4));
            LDSM4(A4, A5, A6, A7, aB1 + ((c16 ^ (aRow1 & 7)) << 4));
            uint32_t bc16 = 2 * (uint32_t)ks + bHalf;
            uint32_t bA0  = bBase + ((bc16 ^ bRowL) << 4);
#pragma unroll
            for (int nt = 0; nt < 9; ++nt) {
                uint32_t B0, B1;
                LDSM2(B0, B1, bA0 + (uint32_t)nt * 1024);
                MMA16816(acc + nt * 8,     A0, A1, A2, A3, B0, B1);
                MMA16816(acc + nt * 8 + 4, A4, A5, A6, A7, B0, B1);
            }
        }
    }

    // ---- epilogue: drain async, then stage P/Q to smem and combine ----
    CP_WAIT0();                        // no cp.async may touch reused smem
    __syncthreads();
    float* sC = (float*)(smem + SM_A); // [2][128][CPITCH] = 77824 B
    {
        float* base = sC + (size_t)part * 128 * CPITCH + mrb * CPITCH;
#pragma unroll
        for (int rh = 0; rh < 2; ++rh) {
            int r1 = rh * 16 + (lane >> 2);
            int r2 = r1 + 8;
#pragma unroll
            for (int nt = 0; nt < 9; ++nt) {
                int col = nt * 8 + 2 * (lane & 3);
                *(float2*)(base + r1 * CPITCH + col) =
                    make_float2(acc[nt * 8 + rh * 4 + 0], acc[nt * 8 + rh * 4 + 1]);
                *(float2*)(base + r2 * CPITCH + col) =
                    make_float2(acc[nt * 8 + rh * 4 + 2], acc[nt * 8 + rh * 4 + 3]);
            }
        }
    }
    __syncthreads();
    {
        int row  = tid >> 1, half = tid & 1;
        float es = sES[row], fs = sFS[row];
        const float* pR = sC + row * CPITCH;
        const float* qR = sC + 128 * CPITCH + row * CPITCH;
        float4* o4 = (float4*)(&g_pacc[sp][i0 + row][half * 32]);
#pragma unroll
        for (int n = 0; n < 32; n += 4) {
            int nn = half * 32 + n;
            float4 v;
            v.x = es * pR[nn + 0] + fs * qR[nn + 0];
            v.y = es * pR[nn + 1] + fs * qR[nn + 1];
            v.z = es * pR[nn + 2] + fs * qR[nn + 2];
            v.w = es * pR[nn + 3] + fs * qR[nn + 3];
            o4[n >> 2] = v;
        }
        if (half == 0)
            g_pl[sp][i0 + row] = es * pR[64] + fs * qR[64];
    }
}

// ---------------------------------------------------------------------------
// K4: combine splits, normalize, ELU
// ---------------------------------------------------------------------------
__global__ __launch_bounds__(256) void k_final(float* __restrict__ out) {
    int idx = blockIdx.x * 256 + threadIdx.x;
    int i = idx >> 5, l = idx & 31;
    float a0 = 0.f, a1 = 0.f, ls = 0.f;
#pragma unroll
    for (int sp = 0; sp < JSPLIT; ++sp) {
        float2 p = *(const float2*)(&g_pacc[sp][i][2 * l]);
        a0 += p.x; a1 += p.y;
        ls += g_pl[sp][i];
    }
    float inv = 1.0f / ls;
    a0 *= inv; a1 *= inv;
    a0 = (a0 > 0.f) ? a0 : (fast_exp(a0) - 1.f);
    a1 = (a1 > 0.f) ? a1 : (fast_exp(a1) - 1.f);
    *(float2*)(out + i * 64 + 2 * l) = make_float2(a0, a1);
}

extern "C" void kernel_launch(void* const* d_in, const int* in_sizes, int n_in,
                              void* d_out, int out_size) {
    const float* inp = (const float*)d_in[0];
    const int*   adj = (const int*)d_in[1];
    const float* W   = (const float*)d_in[2];
    const float* a   = (const float*)d_in[3];
    float*       out = (float*)d_out;

    cudaFuncSetAttribute(k_attn, cudaFuncAttributeMaxDynamicSharedMemorySize,
                         SM_TOT);

    k_wh<<<NROWS / 8, 128>>>(inp, W, a);
    k_prep<<<NCHUNKS, 256>>>();
    k_attn<<<64 * JSPLIT, 256, SM_TOT>>>(adj);
    k_final<<<(NROWS * 32) / 256, 256>>>(out);
}

// round 14
// speedup vs baseline: 1.1153x; 1.1153x over previous
#include <cuda_runtime.h>
#include <cuda_bf16.h>
#include <cstdint>
#include <cstddef>

#define NROWS 8192
#define FD 64
#define CJ 128
#define TILE_I 128
#define JSPLIT 8
#define NCHUNKS 64
#define BIMG 36864            // per-chunk B image: 144 rows x 256 B (U;V)

typedef unsigned long long ull;

__device__ float g_Wh[NROWS * FD];
__device__ float g_s[NROWS], g_d[NROWS];
__device__ float g_es[NROWS], g_fs[NROWS], g_ed[NROWS], g_fd[NROWS];
__device__ uint8_t g_UV[NCHUNKS * BIMG];          // prepacked swizzled B images
__device__ float g_pacc[JSPLIT][NROWS][FD];
__device__ float g_pl[JSPLIT][NROWS];

__device__ __forceinline__ float fast_exp(float t) {
    float x = t * 1.4426950408889634f;
    x = fminf(fmaxf(x, -126.0f), 126.0f);
    float c = x + 12582912.0f;
    int   ic = __float_as_int(c);
    float f  = x - (c - 12582912.0f);
    float y  = f * 0.6931471805599453f;
    float p = 1.3888889e-3f;
    p = fmaf(p, y, 8.3333333e-3f);
    p = fmaf(p, y, 4.1666667e-2f);
    p = fmaf(p, y, 1.6666667e-1f);
    p = fmaf(p, y, 0.5f);
    p = fmaf(p, y, 1.0f);
    p = fmaf(p, y, 1.0f);
    return p * __int_as_float(((ic & 0x7FFFFF) - 0x400000 + 127) << 23);
}

__device__ __forceinline__ uint32_t smem_u32(const void* p) {
    uint32_t a;
    asm("{ .reg .u64 t; cvta.to.shared.u64 t, %1; cvt.u32.u64 %0, t; }"
        : "=r"(a) : "l"(p));
    return a;
}
#define LDSM4(a0, a1, a2, a3, ad)                                              \
    asm volatile("ldmatrix.sync.aligned.m8n8.x4.shared.b16 {%0,%1,%2,%3}, [%4];" \
                 : "=r"(a0), "=r"(a1), "=r"(a2), "=r"(a3) : "r"(ad))
#define LDSM2(b0, b1, ad)                                                      \
    asm volatile("ldmatrix.sync.aligned.m8n8.x2.shared.b16 {%0,%1}, [%2];"     \
                 : "=r"(b0), "=r"(b1) : "r"(ad))
#define MMA16816(d, a0, a1, a2, a3, b0, b1)                                    \
    asm volatile("mma.sync.aligned.m16n8k16.row.col.f32.bf16.bf16.f32 "        \
                 "{%0,%1,%2,%3}, {%4,%5,%6,%7}, {%8,%9}, {%0,%1,%2,%3};"       \
                 : "+f"((d)[0]), "+f"((d)[1]), "+f"((d)[2]), "+f"((d)[3])      \
                 : "r"(a0), "r"(a1), "r"(a2), "r"(a3), "r"(b0), "r"(b1))
#define PF_L2(p) asm volatile("prefetch.global.L2 [%0];" :: "l"(p))

// ---------------------------------------------------------------------------
// K1: Wh = X@W, fused s/d and exp-factor tables
// ---------------------------------------------------------------------------
__global__ __launch_bounds__(128) void k_wh(const float* __restrict__ inp,
                                            const float* __restrict__ W,
                                            const float* __restrict__ a) {
    __shared__ float sIn[8 * 65];
    __shared__ float sW[64 * 64];
    __shared__ float sA[128];
    int tid = threadIdx.x;
    int i0  = blockIdx.x * 8;
    for (int idx = tid; idx < 512; idx += 128) {
        int r = idx >> 6, k = idx & 63;
        sIn[r * 65 + k] = inp[i0 * 64 + idx];
    }
    const float4* W4 = (const float4*)W;
    float4* sW4w = (float4*)sW;
#pragma unroll
    for (int q = 0; q < 8; ++q) sW4w[tid + q * 128] = W4[tid + q * 128];
    if (tid < 128) sA[tid] = a[tid];
    __syncthreads();

    int r = tid >> 4, fg = tid & 15;
    float acc[4];
#pragma unroll
    for (int q = 0; q < 4; ++q) acc[q] = 0.f;
    const float4* sW4 = (const float4*)sW;
#pragma unroll 16
    for (int k = 0; k < 64; ++k) {
        float  x = sIn[r * 65 + k];
        float4 w = sW4[k * 16 + fg];
        acc[0] = fmaf(x, w.x, acc[0]);
        acc[1] = fmaf(x, w.y, acc[1]);
        acc[2] = fmaf(x, w.z, acc[2]);
        acc[3] = fmaf(x, w.w, acc[3]);
    }
    int row = i0 + r;
    float ps = 0.f, pd = 0.f;
#pragma unroll
    for (int q = 0; q < 4; ++q) {
        ps = fmaf(acc[q], sA[fg * 4 + q], ps);
        pd = fmaf(acc[q], sA[64 + fg * 4 + q], pd);
    }
    *(float4*)(g_Wh + row * 64 + fg * 4) =
        make_float4(acc[0], acc[1], acc[2], acc[3]);
#pragma unroll
    for (int o = 1; o < 16; o <<= 1) {
        ps += __shfl_xor_sync(0xffffffffu, ps, o, 16);
        pd += __shfl_xor_sync(0xffffffffu, pd, o, 16);
    }
    if (fg == 0) {
        float sc = fminf(fmaxf(ps, -87.f), 80.f);
        float dc = fminf(fmaxf(pd, -87.f), 80.f);
        g_s[row] = ps; g_d[row] = pd;
        g_es[row] = fast_exp(sc);        g_fs[row] = fast_exp(0.2f * sc);
        g_ed[row] = fast_exp(dc);        g_fd[row] = fast_exp(0.2f * dc);
    }
}

// ---------------------------------------------------------------------------
// K2: build pre-swizzled bf16 B images per chunk (R8 version)
// ---------------------------------------------------------------------------
__device__ __forceinline__ uint32_t pk_bf2(float lo, float hi) {
    uint32_t l = (uint32_t)__bfloat16_as_ushort(__float2bfloat16_rn(lo));
    uint32_t h = (uint32_t)__bfloat16_as_ushort(__float2bfloat16_rn(hi));
    return l | (h << 16);
}
__global__ __launch_bounds__(256) void k_prep() {
    int c  = blockIdx.x;
    int jb = c * CJ;
    uint8_t* base = g_UV + (size_t)c * BIMG;
    for (int idx = threadIdx.x; idx < 72 * 64; idx += 256) {
        int n = idx >> 6, jp = idx & 63, j = 2 * jp;
        float e0 = g_ed[jb + j], e1 = g_ed[jb + j + 1];
        float f0 = g_fd[jb + j], f1 = g_fd[jb + j + 1];
        float u0, u1, v0, v1;
        if (n < 64) {
            float w0 = g_Wh[(size_t)(jb + j) * 64 + n];
            float w1 = g_Wh[(size_t)(jb + j + 1) * 64 + n];
            u0 = e0 * w0; u1 = e1 * w1; v0 = f0 * w0; v1 = f1 * w1;
        } else if (n == 64) { u0 = e0; u1 = e1; v0 = f0; v1 = f1; }
        else { u0 = u1 = v0 = v1 = 0.f; }
        uint32_t c16 = (uint32_t)(jp >> 2);
        uint32_t sw  = ((c16 ^ (uint32_t)(n & 7)) << 4) + (jp & 3) * 4;
        *(uint32_t*)(base + n * 256 + sw)         = pk_bf2(u0, u1);
        *(uint32_t*)(base + (72 + n) * 256 + sw)  = pk_bf2(v0, v1);
    }
}

// ---------------------------------------------------------------------------
// K3: exact binary masks + HMMA (R8 structure) + L2 prefetch of next adj
// chunk + paired-B ldmatrix.x4.
// ---------------------------------------------------------------------------
#define SM_S   0
#define SM_ES  512
#define SM_FS  1024
#define SM_A   2048
#define SM_B   (SM_A + 128 * 512)        // 67584
#define SM_TOT (SM_B + BIMG)             // 104448
#define CPITCH 76

__global__ __launch_bounds__(256, 2) void k_attn(const int* __restrict__ adj) {
    extern __shared__ char smem[];
    float* sS  = (float*)(smem + SM_S);
    float* sES = (float*)(smem + SM_ES);
    float* sFS = (float*)(smem + SM_FS);
    int tid = threadIdx.x, wid = tid >> 5, lane = tid & 31;
    int itile = blockIdx.x & 63, sp = blockIdx.x >> 6;
    int i0 = itile * TILE_I;
    int rb = wid * 16;                 // build rows (all warps build C and D)

    if (tid < 128) {
        sS[tid]  = g_s[i0 + tid];
        sES[tid] = g_es[i0 + tid];
        sFS[tid] = g_fs[i0 + tid];
    }

    int part = wid >> 2;               // 0: C@U, 1: D@V
    int mrb  = (wid & 3) * 32;

    float acc[72];
#pragma unroll
    for (int q = 0; q < 72; ++q) acc[q] = 0.f;

    uint32_t sAu = smem_u32(smem) + SM_A;
    uint32_t sBu = smem_u32(smem) + SM_B;
    uint32_t aRow0 = (uint32_t)mrb + (lane & 15);
    uint32_t aRow1 = aRow0 + 16;
    uint32_t aB0 = sAu + aRow0 * 512;
    uint32_t aB1 = sAu + aRow1 * 512;
    uint32_t cBase = (uint32_t)part * 16 + (uint32_t)(lane >> 4);
    // paired-B ldmatrix.x4 addressing: lane>>4 = n-tile within pair,
    // (lane>>3)&1 = k-half, lane&7 = row within 8-row tile
    uint32_t bRow = (uint32_t)(lane & 7);
    uint32_t bK   = (uint32_t)((lane >> 3) & 1);
    uint32_t bNt  = (uint32_t)(lane >> 4);
    uint32_t bPart = sBu + (uint32_t)part * 72 * 256 + bNt * 2048 + bRow * 256;
    // LDSM2 (tile 8) uses lanes 0-15 only: bRow/bK as before
    uint32_t b8Base = sBu + (uint32_t)part * 72 * 256 + 8 * 2048 + bRow * 256;

    int j0 = 4 * lane;
    // L2 prefetch addressing: thread t covers row tid>>1, 2 x 128B lines
    const int* pfBase = adj + (size_t)(i0 + (tid >> 1)) * NROWS + (tid & 1) * 64;

    for (int cc = 0; cc < 8; ++cc) {
        int gch = sp * 8 + cc;
        int jb  = gch * CJ;
        __syncthreads();
        {   // copy prepacked B image (36864 B = 2304 uint4)
            const uint4* src = (const uint4*)(g_UV + (size_t)gch * BIMG);
            uint4* dst = (uint4*)(smem + SM_B);
#pragma unroll
            for (int q = 0; q < 9; ++q) dst[tid + q * 256] = src[tid + q * 256];
        }
        // mask build: 16 rows per warp, 4 j per lane
        float4 dv = *(const float4*)(g_d + jb + j0);
        const int4* ap = (const int4*)(adj + (size_t)(i0 + rb) * NROWS + jb) + lane;
#pragma unroll
        for (int g = 0; g < 4; ++g) {
            int4 a4[4];
#pragma unroll
            for (int r = 0; r < 4; ++r)
                a4[r] = __ldg(ap + (size_t)(g * 4 + r) * (NROWS / 4));
#pragma unroll
            for (int r = 0; r < 4; ++r) {
                uint32_t R  = (uint32_t)rb + g * 4 + r;
                float    sr = sS[R];
                float t0 = sr + dv.x, t1 = sr + dv.y;
                float t2 = sr + dv.z, t3 = sr + dv.w;
                uint32_t h01 = (t0 > 0.f ? 0x3F80u : 0u) | (t1 > 0.f ? 0x3F800000u : 0u);
                uint32_t h23 = (t2 > 0.f ? 0x3F80u : 0u) | (t3 > 0.f ? 0x3F800000u : 0u);
                uint32_t m01 = (uint32_t)a4[r].x * 0xFFFFu + (uint32_t)a4[r].y * 0xFFFF0000u;
                uint32_t m23 = (uint32_t)a4[r].z * 0xFFFFu + (uint32_t)a4[r].w * 0xFFFF0000u;
                uint32_t off = R * 512 + ((((uint32_t)(lane >> 1)) ^ (R & 7)) << 4)
                             + (uint32_t)(lane & 1) * 8;
                *(uint2*)(smem + SM_A + off) = make_uint2(h01 & m01, h23 & m23);
                *(uint2*)(smem + SM_A + off + 256) =
                    make_uint2((h01 ^ 0x3F803F80u) & m01, (h23 ^ 0x3F803F80u) & m23);
            }
        }
        __syncthreads();
        // L2 prefetch of next chunk's adj — streams under the MMA phase
        if (cc < 7) {
            const int* pf = pfBase + jb + CJ;
            PF_L2(pf);
            PF_L2(pf + 32);
        }

        // HMMA: this warp's part only, 32 rows, 9 n-tiles (4x paired + 1)
#pragma unroll
        for (int ks = 0; ks < 8; ++ks) {
            uint32_t c16 = cBase + 2 * (uint32_t)ks;
            uint32_t A0, A1, A2, A3, A4, A5, A6, A7;
            LDSM4(A0, A1, A2, A3, aB0 + ((c16 ^ (aRow0 & 7)) << 4));
            LDSM4(A4, A5, A6, A7, aB1 + ((c16 ^ (aRow1 & 7)) << 4));
            uint32_t bc16 = 2 * (uint32_t)ks + bK;
            uint32_t bSw  = ((bc16 ^ bRow) << 4);
#pragma unroll
            for (int ntp = 0; ntp < 4; ++ntp) {
                uint32_t B0, B1, B2, B3;
                LDSM4(B0, B1, B2, B3, bPart + (uint32_t)ntp * 4096 + bSw);
                MMA16816(acc + ntp * 16,      A0, A1, A2, A3, B0, B1);
                MMA16816(acc + ntp * 16 + 4,  A4, A5, A6, A7, B0, B1);
                MMA16816(acc + ntp * 16 + 8,  A0, A1, A2, A3, B2, B3);
                MMA16816(acc + ntp * 16 + 12, A4, A5, A6, A7, B2, B3);
            }
            {   // 9th n-tile (sum column)
                uint32_t B0, B1;
                LDSM2(B0, B1, b8Base + bSw);
                MMA16816(acc + 64, A0, A1, A2, A3, B0, B1);
                MMA16816(acc + 68, A4, A5, A6, A7, B0, B1);
            }
        }
    }

    // ---- epilogue: stage P/Q to smem, combine Es*P + Fs*Q ----
    // acc layout: nt 0..7 at acc[(nt>>1)*16 + (nt&1)*8 + rh*4 + q], nt8 at 64.
    __syncthreads();                   // A/B tiles dead; reuse as staging
    float* sC = (float*)(smem + SM_A); // [2][128][CPITCH]
    {
        float* base = sC + (size_t)part * 128 * CPITCH + mrb * CPITCH;
#pragma unroll
        for (int rh = 0; rh < 2; ++rh) {
            int r1 = rh * 16 + (lane >> 2);
            int r2 = r1 + 8;
#pragma unroll
            for (int nt = 0; nt < 9; ++nt) {
                int aidx = (nt < 8) ? ((nt >> 1) * 16 + (nt & 1) * 8 + rh * 4) : (64 + rh * 4);
                int col = nt * 8 + 2 * (lane & 3);
                *(float2*)(base + r1 * CPITCH + col) =
                    make_float2(acc[aidx + 0], acc[aidx + 1]);
                *(float2*)(base + r2 * CPITCH + col) =
                    make_float2(acc[aidx + 2], acc[aidx + 3]);
            }
        }
    }
    __syncthreads();
    {
        int row  = tid >> 1, half = tid & 1;
        float es = sES[row], fs = sFS[row];
        const float* pR = sC + row * CPITCH;
        const float* qR = sC + 128 * CPITCH + row * CPITCH;
        float4* o4 = (float4*)(&g_pacc[sp][i0 + row][half * 32]);
#pragma unroll
        for (int n = 0; n < 32; n += 4) {
            int nn = half * 32 + n;
            float4 v;
            v.x = es * pR[nn + 0] + fs * qR[nn + 0];
            v.y = es * pR[nn + 1] + fs * qR[nn + 1];
            v.z = es * pR[nn + 2] + fs * qR[nn + 2];
            v.w = es * pR[nn + 3] + fs * qR[nn + 3];
            o4[n >> 2] = v;
        }
        if (half == 0)
            g_pl[sp][i0 + row] = es * pR[64] + fs * qR[64];
    }
}

// ---------------------------------------------------------------------------
// K4: combine splits, normalize, ELU
// ---------------------------------------------------------------------------
__global__ __launch_bounds__(256) void k_final(float* __restrict__ out) {
    int idx = blockIdx.x * 256 + threadIdx.x;
    int i = idx >> 5, l = idx & 31;
    float a0 = 0.f, a1 = 0.f, ls = 0.f;
#pragma unroll
    for (int sp = 0; sp < JSPLIT; ++sp) {
        float2 p = *(const float2*)(&g_pacc[sp][i][2 * l]);
        a0 += p.x; a1 += p.y;
        ls += g_pl[sp][i];
    }
    float inv = 1.0f / ls;
    a0 *= inv; a1 *= inv;
    a0 = (a0 > 0.f) ? a0 : (fast_exp(a0) - 1.f);
    a1 = (a1 > 0.f) ? a1 : (fast_exp(a1) - 1.f);
    *(float2*)(out + i * 64 + 2 * l) = make_float2(a0, a1);
}

extern "C" void kernel_launch(void* const* d_in, const int* in_sizes, int n_in,
                              void* d_out, int out_size) {
    const float* inp = (const float*)d_in[0];
    const int*   adj = (const int*)d_in[1];
    const float* W   = (const float*)d_in[2];
    const float* a   = (const float*)d_in[3];
    float*       out = (float*)d_out;

    cudaFuncSetAttribute(k_attn, cudaFuncAttributeMaxDynamicSharedMemorySize,
                         SM_TOT);

    k_wh<<<NROWS / 8, 128>>>(inp, W, a);
    k_prep<<<NCHUNKS, 256>>>();
    k_attn<<<64 * JSPLIT, 256, SM_TOT>>>(adj);
    k_final<<<(NROWS * 32) / 256, 256>>>(out);
}

// round 15
// speedup vs baseline: 1.3033x; 1.1685x over previous
#include <cuda_runtime.h>
#include <cuda_bf16.h>
#include <cstdint>
#include <cstddef>

#define NROWS 8192
#define FD 64
#define CJ 128
#define TILE_I 128
#define JSPLIT 8
#define NCHUNKS 64
#define BIMG 36864            // per-chunk B image: 144 rows x 256 B (U;V)

typedef unsigned long long ull;

__device__ float g_Wh[NROWS * FD];
__device__ float g_s[NROWS], g_d[NROWS];
__device__ float g_es[NROWS], g_fs[NROWS], g_ed[NROWS], g_fd[NROWS];
__device__ uint8_t g_UV[NCHUNKS * BIMG];          // prepacked swizzled B images
__device__ float g_pacc[JSPLIT][NROWS][FD];
__device__ float g_pl[JSPLIT][NROWS];

__device__ __forceinline__ float fast_exp(float t) {
    float x = t * 1.4426950408889634f;
    x = fminf(fmaxf(x, -126.0f), 126.0f);
    float c = x + 12582912.0f;
    int   ic = __float_as_int(c);
    float f  = x - (c - 12582912.0f);
    float y  = f * 0.6931471805599453f;
    float p = 1.3888889e-3f;
    p = fmaf(p, y, 8.3333333e-3f);
    p = fmaf(p, y, 4.1666667e-2f);
    p = fmaf(p, y, 1.6666667e-1f);
    p = fmaf(p, y, 0.5f);
    p = fmaf(p, y, 1.0f);
    p = fmaf(p, y, 1.0f);
    return p * __int_as_float(((ic & 0x7FFFFF) - 0x400000 + 127) << 23);
}

__device__ __forceinline__ uint32_t smem_u32(const void* p) {
    uint32_t a;
    asm("{ .reg .u64 t; cvta.to.shared.u64 t, %1; cvt.u32.u64 %0, t; }"
        : "=r"(a) : "l"(p));
    return a;
}
#define LDSM4(a0, a1, a2, a3, ad)                                              \
    asm volatile("ldmatrix.sync.aligned.m8n8.x4.shared.b16 {%0,%1,%2,%3}, [%4];" \
                 : "=r"(a0), "=r"(a1), "=r"(a2), "=r"(a3) : "r"(ad))
#define LDSM2(b0, b1, ad)                                                      \
    asm volatile("ldmatrix.sync.aligned.m8n8.x2.shared.b16 {%0,%1}, [%2];"     \
                 : "=r"(b0), "=r"(b1) : "r"(ad))
#define MMA16816(d, a0, a1, a2, a3, b0, b1)                                    \
    asm volatile("mma.sync.aligned.m16n8k16.row.col.f32.bf16.bf16.f32 "        \
                 "{%0,%1,%2,%3}, {%4,%5,%6,%7}, {%8,%9}, {%0,%1,%2,%3};"       \
                 : "+f"((d)[0]), "+f"((d)[1]), "+f"((d)[2]), "+f"((d)[3])      \
                 : "r"(a0), "r"(a1), "r"(a2), "r"(a3), "r"(b0), "r"(b1))
#define PF_L2(p) asm volatile("prefetch.global.L2 [%0];" :: "l"(p))

// ---------------------------------------------------------------------------
// K1: Wh = X@W, fused s/d and exp-factor tables
// ---------------------------------------------------------------------------
__global__ __launch_bounds__(128) void k_wh(const float* __restrict__ inp,
                                            const float* __restrict__ W,
                                            const float* __restrict__ a) {
    __shared__ float sIn[8 * 65];
    __shared__ float sW[64 * 64];
    __shared__ float sA[128];
    int tid = threadIdx.x;
    int i0  = blockIdx.x * 8;
    for (int idx = tid; idx < 512; idx += 128) {
        int r = idx >> 6, k = idx & 63;
        sIn[r * 65 + k] = inp[i0 * 64 + idx];
    }
    const float4* W4 = (const float4*)W;
    float4* sW4w = (float4*)sW;
#pragma unroll
    for (int q = 0; q < 8; ++q) sW4w[tid + q * 128] = W4[tid + q * 128];
    if (tid < 128) sA[tid] = a[tid];
    __syncthreads();

    int r = tid >> 4, fg = tid & 15;
    float acc[4];
#pragma unroll
    for (int q = 0; q < 4; ++q) acc[q] = 0.f;
    const float4* sW4 = (const float4*)sW;
#pragma unroll 16
    for (int k = 0; k < 64; ++k) {
        float  x = sIn[r * 65 + k];
        float4 w = sW4[k * 16 + fg];
        acc[0] = fmaf(x, w.x, acc[0]);
        acc[1] = fmaf(x, w.y, acc[1]);
        acc[2] = fmaf(x, w.z, acc[2]);
        acc[3] = fmaf(x, w.w, acc[3]);
    }
    int row = i0 + r;
    float ps = 0.f, pd = 0.f;
#pragma unroll
    for (int q = 0; q < 4; ++q) {
        ps = fmaf(acc[q], sA[fg * 4 + q], ps);
        pd = fmaf(acc[q], sA[64 + fg * 4 + q], pd);
    }
    *(float4*)(g_Wh + row * 64 + fg * 4) =
        make_float4(acc[0], acc[1], acc[2], acc[3]);
#pragma unroll
    for (int o = 1; o < 16; o <<= 1) {
        ps += __shfl_xor_sync(0xffffffffu, ps, o, 16);
        pd += __shfl_xor_sync(0xffffffffu, pd, o, 16);
    }
    if (fg == 0) {
        float sc = fminf(fmaxf(ps, -87.f), 80.f);
        float dc = fminf(fmaxf(pd, -87.f), 80.f);
        g_s[row] = ps; g_d[row] = pd;
        g_es[row] = fast_exp(sc);        g_fs[row] = fast_exp(0.2f * sc);
        g_ed[row] = fast_exp(dc);        g_fd[row] = fast_exp(0.2f * dc);
    }
}

// ---------------------------------------------------------------------------
// K2: build pre-swizzled bf16 B images per chunk (R8 version)
// ---------------------------------------------------------------------------
__device__ __forceinline__ uint32_t pk_bf2(float lo, float hi) {
    uint32_t l = (uint32_t)__bfloat16_as_ushort(__float2bfloat16_rn(lo));
    uint32_t h = (uint32_t)__bfloat16_as_ushort(__float2bfloat16_rn(hi));
    return l | (h << 16);
}
__global__ __launch_bounds__(256) void k_prep() {
    int c  = blockIdx.x;
    int jb = c * CJ;
    uint8_t* base = g_UV + (size_t)c * BIMG;
    for (int idx = threadIdx.x; idx < 72 * 64; idx += 256) {
        int n = idx >> 6, jp = idx & 63, j = 2 * jp;
        float e0 = g_ed[jb + j], e1 = g_ed[jb + j + 1];
        float f0 = g_fd[jb + j], f1 = g_fd[jb + j + 1];
        float u0, u1, v0, v1;
        if (n < 64) {
            float w0 = g_Wh[(size_t)(jb + j) * 64 + n];
            float w1 = g_Wh[(size_t)(jb + j + 1) * 64 + n];
            u0 = e0 * w0; u1 = e1 * w1; v0 = f0 * w0; v1 = f1 * w1;
        } else if (n == 64) { u0 = e0; u1 = e1; v0 = f0; v1 = f1; }
        else { u0 = u1 = v0 = v1 = 0.f; }
        uint32_t c16 = (uint32_t)(jp >> 2);
        uint32_t sw  = ((c16 ^ (uint32_t)(n & 7)) << 4) + (jp & 3) * 4;
        *(uint32_t*)(base + n * 256 + sw)         = pk_bf2(u0, u1);
        *(uint32_t*)(base + (72 + n) * 256 + sw)  = pk_bf2(v0, v1);
    }
}

// ---------------------------------------------------------------------------
// K3: exact binary masks + HMMA — EXACT R8 structure; sole addition is the
// L2 prefetch of next chunk's adj issued before the MMA phase.
// ---------------------------------------------------------------------------
#define SM_S   0
#define SM_ES  512
#define SM_FS  1024
#define SM_A   2048
#define SM_B   (SM_A + 128 * 512)        // 67584
#define SM_TOT (SM_B + BIMG)             // 104448
#define CPITCH 76

__global__ __launch_bounds__(256, 2) void k_attn(const int* __restrict__ adj) {
    extern __shared__ char smem[];
    float* sS  = (float*)(smem + SM_S);
    float* sES = (float*)(smem + SM_ES);
    float* sFS = (float*)(smem + SM_FS);
    int tid = threadIdx.x, wid = tid >> 5, lane = tid & 31;
    int itile = blockIdx.x & 63, sp = blockIdx.x >> 6;
    int i0 = itile * TILE_I;
    int rb = wid * 16;                 // build rows (all warps build C and D)

    if (tid < 128) {
        sS[tid]  = g_s[i0 + tid];
        sES[tid] = g_es[i0 + tid];
        sFS[tid] = g_fs[i0 + tid];
    }

    int part = wid >> 2;               // 0: C@U, 1: D@V
    int mrb  = (wid & 3) * 32;

    float acc[72];
#pragma unroll
    for (int q = 0; q < 72; ++q) acc[q] = 0.f;

    uint32_t sAu = smem_u32(smem) + SM_A;
    uint32_t sBu = smem_u32(smem) + SM_B;
    uint32_t aRow0 = (uint32_t)mrb + (lane & 15);
    uint32_t aRow1 = aRow0 + 16;
    uint32_t aB0 = sAu + aRow0 * 512;
    uint32_t aB1 = sAu + aRow1 * 512;
    uint32_t cBase = (uint32_t)part * 16 + (uint32_t)(lane >> 4);
    uint32_t bRowL = (uint32_t)(lane & 7);
    uint32_t bHalf = (uint32_t)((lane >> 3) & 1);
    uint32_t bBase = sBu + bRowL * 256 + (uint32_t)part * 72 * 256;

    int j0 = 4 * lane;
    // L2 prefetch addressing: thread t covers row tid>>1, 2 x 128B lines
    const int* pfBase = adj + (size_t)(i0 + (tid >> 1)) * NROWS + (tid & 1) * 64;

    for (int cc = 0; cc < 8; ++cc) {
        int gch = sp * 8 + cc;
        int jb  = gch * CJ;
        __syncthreads();
        {   // copy prepacked B image (36864 B = 2304 uint4)
            const uint4* src = (const uint4*)(g_UV + (size_t)gch * BIMG);
            uint4* dst = (uint4*)(smem + SM_B);
#pragma unroll
            for (int q = 0; q < 9; ++q) dst[tid + q * 256] = src[tid + q * 256];
        }
        // mask build: 16 rows per warp, 4 j per lane
        float4 dv = *(const float4*)(g_d + jb + j0);
        const int4* ap = (const int4*)(adj + (size_t)(i0 + rb) * NROWS + jb) + lane;
#pragma unroll
        for (int g = 0; g < 4; ++g) {
            int4 a4[4];
#pragma unroll
            for (int r = 0; r < 4; ++r)
                a4[r] = __ldg(ap + (size_t)(g * 4 + r) * (NROWS / 4));
#pragma unroll
            for (int r = 0; r < 4; ++r) {
                uint32_t R  = (uint32_t)rb + g * 4 + r;
                float    sr = sS[R];
                float t0 = sr + dv.x, t1 = sr + dv.y;
                float t2 = sr + dv.z, t3 = sr + dv.w;
                uint32_t h01 = (t0 > 0.f ? 0x3F80u : 0u) | (t1 > 0.f ? 0x3F800000u : 0u);
                uint32_t h23 = (t2 > 0.f ? 0x3F80u : 0u) | (t3 > 0.f ? 0x3F800000u : 0u);
                uint32_t m01 = (uint32_t)a4[r].x * 0xFFFFu + (uint32_t)a4[r].y * 0xFFFF0000u;
                uint32_t m23 = (uint32_t)a4[r].z * 0xFFFFu + (uint32_t)a4[r].w * 0xFFFF0000u;
                uint32_t off = R * 512 + ((((uint32_t)(lane >> 1)) ^ (R & 7)) << 4)
                             + (uint32_t)(lane & 1) * 8;
                *(uint2*)(smem + SM_A + off) = make_uint2(h01 & m01, h23 & m23);
                *(uint2*)(smem + SM_A + off + 256) =
                    make_uint2((h01 ^ 0x3F803F80u) & m01, (h23 ^ 0x3F803F80u) & m23);
            }
        }
        __syncthreads();
        // L2 prefetch of next chunk's adj — streams under the MMA phase
        if (cc < 7) {
            const int* pf = pfBase + jb + CJ;
            PF_L2(pf);
            PF_L2(pf + 32);
        }

        // HMMA: this warp's part only, 32 rows, 9 n-tiles (R8 loop shape)
#pragma unroll
        for (int ks = 0; ks < 8; ++ks) {
            uint32_t c16 = cBase + 2 * (uint32_t)ks;
            uint32_t A0, A1, A2, A3, A4, A5, A6, A7;
            LDSM4(A0, A1, A2, A3, aB0 + ((c16 ^ (aRow0 & 7)) << 4));
            LDSM4(A4, A5, A6, A7, aB1 + ((c16 ^ (aRow1 & 7)) << 4));
            uint32_t bc16 = 2 * (uint32_t)ks + bHalf;
            uint32_t bA0  = bBase + ((bc16 ^ bRowL) << 4);
#pragma unroll
            for (int nt = 0; nt < 9; ++nt) {
                uint32_t B0, B1;
                LDSM2(B0, B1, bA0 + (uint32_t)nt * 2048);
                MMA16816(acc + nt * 8,     A0, A1, A2, A3, B0, B1);
                MMA16816(acc + nt * 8 + 4, A4, A5, A6, A7, B0, B1);
            }
        }
    }

    // ---- epilogue: stage P/Q to smem, combine Es*P + Fs*Q (R8 layout) ----
    __syncthreads();                   // A/B tiles dead; reuse as staging
    float* sC = (float*)(smem + SM_A); // [2][128][CPITCH]
    {
        float* base = sC + (size_t)part * 128 * CPITCH + mrb * CPITCH;
#pragma unroll
        for (int rh = 0; rh < 2; ++rh) {
            int r1 = rh * 16 + (lane >> 2);
            int r2 = r1 + 8;
#pragma unroll
            for (int nt = 0; nt < 9; ++nt) {
                int col = nt * 8 + 2 * (lane & 3);
                *(float2*)(base + r1 * CPITCH + col) =
                    make_float2(acc[nt * 8 + rh * 4 + 0], acc[nt * 8 + rh * 4 + 1]);
                *(float2*)(base + r2 * CPITCH + col) =
                    make_float2(acc[nt * 8 + rh * 4 + 2], acc[nt * 8 + rh * 4 + 3]);
            }
        }
    }
    __syncthreads();
    {
        int row  = tid >> 1, half = tid & 1;
        float es = sES[row], fs = sFS[row];
        const float* pR = sC + row * CPITCH;
        const float* qR = sC + 128 * CPITCH + row * CPITCH;
        float4* o4 = (float4*)(&g_pacc[sp][i0 + row][half * 32]);
#pragma unroll
        for (int n = 0; n < 32; n += 4) {
            int nn = half * 32 + n;
            float4 v;
            v.x = es * pR[nn + 0] + fs * qR[nn + 0];
            v.y = es * pR[nn + 1] + fs * qR[nn + 1];
            v.z = es * pR[nn + 2] + fs * qR[nn + 2];
            v.w = es * pR[nn + 3] + fs * qR[nn + 3];
            o4[n >> 2] = v;
        }
        if (half == 0)
            g_pl[sp][i0 + row] = es * pR[64] + fs * qR[64];
    }
}

// ---------------------------------------------------------------------------
// K4: combine splits, normalize, ELU
// ---------------------------------------------------------------------------
__global__ __launch_bounds__(256) void k_final(float* __restrict__ out) {
    int idx = blockIdx.x * 256 + threadIdx.x;
    int i = idx >> 5, l = idx & 31;
    float a0 = 0.f, a1 = 0.f, ls = 0.f;
#pragma unroll
    for (int sp = 0; sp < JSPLIT; ++sp) {
        float2 p = *(const float2*)(&g_pacc[sp][i][2 * l]);
        a0 += p.x; a1 += p.y;
        ls += g_pl[sp][i];
    }
    float inv = 1.0f / ls;
    a0 *= inv; a1 *= inv;
    a0 = (a0 > 0.f) ? a0 : (fast_exp(a0) - 1.f);
    a1 = (a1 > 0.f) ? a1 : (fast_exp(a1) - 1.f);
    *(float2*)(out + i * 64 + 2 * l) = make_float2(a0, a1);
}

extern "C" void kernel_launch(void* const* d_in, const int* in_sizes, int n_in,
                              void* d_out, int out_size) {
    const float* inp = (const float*)d_in[0];
    const int*   adj = (const int*)d_in[1];
    const float* W   = (const float*)d_in[2];
    const float* a   = (const float*)d_in[3];
    float*       out = (float*)d_out;

    cudaFuncSetAttribute(k_attn, cudaFuncAttributeMaxDynamicSharedMemorySize,
                         SM_TOT);

    k_wh<<<NROWS / 8, 128>>>(inp, W, a);
    k_prep<<<NCHUNKS, 256>>>();
    k_attn<<<64 * JSPLIT, 256, SM_TOT>>>(adj);
    k_final<<<(NROWS * 32) / 256, 256>>>(out);
}

// round 16
// speedup vs baseline: 1.3686x; 1.0501x over previous
#include <cuda_runtime.h>
#include <cuda_bf16.h>
#include <cstdint>
#include <cstddef>

#define NROWS 8192
#define FD 64
#define CJ 128
#define TILE_I 128
#define JSPLIT 4
#define NCHAIN 16                  // chunks per CTA
#define NCHUNKS 64
#define BIMG 36864            // per-chunk B image: 144 rows x 256 B (U;V)

typedef unsigned long long ull;

__device__ float g_Wh[NROWS * FD];
__device__ float g_s[NROWS], g_d[NROWS];
__device__ float g_es[NROWS], g_fs[NROWS], g_ed[NROWS], g_fd[NROWS];
__device__ uint8_t g_UV[NCHUNKS * BIMG];          // prepacked swizzled B images
__device__ float g_pacc[JSPLIT][NROWS][FD];
__device__ float g_pl[JSPLIT][NROWS];

__device__ __forceinline__ float fast_exp(float t) {
    float x = t * 1.4426950408889634f;
    x = fminf(fmaxf(x, -126.0f), 126.0f);
    float c = x + 12582912.0f;
    int   ic = __float_as_int(c);
    float f  = x - (c - 12582912.0f);
    float y  = f * 0.6931471805599453f;
    float p = 1.3888889e-3f;
    p = fmaf(p, y, 8.3333333e-3f);
    p = fmaf(p, y, 4.1666667e-2f);
    p = fmaf(p, y, 1.6666667e-1f);
    p = fmaf(p, y, 0.5f);
    p = fmaf(p, y, 1.0f);
    p = fmaf(p, y, 1.0f);
    return p * __int_as_float(((ic & 0x7FFFFF) - 0x400000 + 127) << 23);
}

__device__ __forceinline__ uint32_t smem_u32(const void* p) {
    uint32_t a;
    asm("{ .reg .u64 t; cvta.to.shared.u64 t, %1; cvt.u32.u64 %0, t; }"
        : "=r"(a) : "l"(p));
    return a;
}
#define LDSM4(a0, a1, a2, a3, ad)                                              \
    asm volatile("ldmatrix.sync.aligned.m8n8.x4.shared.b16 {%0,%1,%2,%3}, [%4];" \
                 : "=r"(a0), "=r"(a1), "=r"(a2), "=r"(a3) : "r"(ad))
#define LDSM2(b0, b1, ad)                                                      \
    asm volatile("ldmatrix.sync.aligned.m8n8.x2.shared.b16 {%0,%1}, [%2];"     \
                 : "=r"(b0), "=r"(b1) : "r"(ad))
#define MMA16816(d, a0, a1, a2, a3, b0, b1)                                    \
    asm volatile("mma.sync.aligned.m16n8k16.row.col.f32.bf16.bf16.f32 "        \
                 "{%0,%1,%2,%3}, {%4,%5,%6,%7}, {%8,%9}, {%0,%1,%2,%3};"       \
                 : "+f"((d)[0]), "+f"((d)[1]), "+f"((d)[2]), "+f"((d)[3])      \
                 : "r"(a0), "r"(a1), "r"(a2), "r"(a3), "r"(b0), "r"(b1))
#define PF_L2(p) asm volatile("prefetch.global.L2 [%0];" :: "l"(p))

// ---------------------------------------------------------------------------
// K1: Wh = X@W, fused s/d and exp-factor tables
// ---------------------------------------------------------------------------
__global__ __launch_bounds__(128) void k_wh(const float* __restrict__ inp,
                                            const float* __restrict__ W,
                                            const float* __restrict__ a) {
    __shared__ float sIn[8 * 65];
    __shared__ float sW[64 * 64];
    __shared__ float sA[128];
    int tid = threadIdx.x;
    int i0  = blockIdx.x * 8;
    for (int idx = tid; idx < 512; idx += 128) {
        int r = idx >> 6, k = idx & 63;
        sIn[r * 65 + k] = inp[i0 * 64 + idx];
    }
    const float4* W4 = (const float4*)W;
    float4* sW4w = (float4*)sW;
#pragma unroll
    for (int q = 0; q < 8; ++q) sW4w[tid + q * 128] = W4[tid + q * 128];
    if (tid < 128) sA[tid] = a[tid];
    __syncthreads();

    int r = tid >> 4, fg = tid & 15;
    float acc[4];
#pragma unroll
    for (int q = 0; q < 4; ++q) acc[q] = 0.f;
    const float4* sW4 = (const float4*)sW;
#pragma unroll 16
    for (int k = 0; k < 64; ++k) {
        float  x = sIn[r * 65 + k];
        float4 w = sW4[k * 16 + fg];
        acc[0] = fmaf(x, w.x, acc[0]);
        acc[1] = fmaf(x, w.y, acc[1]);
        acc[2] = fmaf(x, w.z, acc[2]);
        acc[3] = fmaf(x, w.w, acc[3]);
    }
    int row = i0 + r;
    float ps = 0.f, pd = 0.f;
#pragma unroll
    for (int q = 0; q < 4; ++q) {
        ps = fmaf(acc[q], sA[fg * 4 + q], ps);
        pd = fmaf(acc[q], sA[64 + fg * 4 + q], pd);
    }
    *(float4*)(g_Wh + row * 64 + fg * 4) =
        make_float4(acc[0], acc[1], acc[2], acc[3]);
#pragma unroll
    for (int o = 1; o < 16; o <<= 1) {
        ps += __shfl_xor_sync(0xffffffffu, ps, o, 16);
        pd += __shfl_xor_sync(0xffffffffu, pd, o, 16);
    }
    if (fg == 0) {
        float sc = fminf(fmaxf(ps, -87.f), 80.f);
        float dc = fminf(fmaxf(pd, -87.f), 80.f);
        g_s[row] = ps; g_d[row] = pd;
        g_es[row] = fast_exp(sc);        g_fs[row] = fast_exp(0.2f * sc);
        g_ed[row] = fast_exp(dc);        g_fd[row] = fast_exp(0.2f * dc);
    }
}

// ---------------------------------------------------------------------------
// K2: build pre-swizzled bf16 B images per chunk (unchanged)
// ---------------------------------------------------------------------------
__device__ __forceinline__ uint32_t pk_bf2(float lo, float hi) {
    uint32_t l = (uint32_t)__bfloat16_as_ushort(__float2bfloat16_rn(lo));
    uint32_t h = (uint32_t)__bfloat16_as_ushort(__float2bfloat16_rn(hi));
    return l | (h << 16);
}
__global__ __launch_bounds__(256) void k_prep() {
    int c  = blockIdx.x;
    int jb = c * CJ;
    uint8_t* base = g_UV + (size_t)c * BIMG;
    for (int idx = threadIdx.x; idx < 72 * 64; idx += 256) {
        int n = idx >> 6, jp = idx & 63, j = 2 * jp;
        float e0 = g_ed[jb + j], e1 = g_ed[jb + j + 1];
        float f0 = g_fd[jb + j], f1 = g_fd[jb + j + 1];
        float u0, u1, v0, v1;
        if (n < 64) {
            float w0 = g_Wh[(size_t)(jb + j) * 64 + n];
            float w1 = g_Wh[(size_t)(jb + j + 1) * 64 + n];
            u0 = e0 * w0; u1 = e1 * w1; v0 = f0 * w0; v1 = f1 * w1;
        } else if (n == 64) { u0 = e0; u1 = e1; v0 = f0; v1 = f1; }
        else { u0 = u1 = v0 = v1 = 0.f; }
        uint32_t c16 = (uint32_t)(jp >> 2);
        uint32_t sw  = ((c16 ^ (uint32_t)(n & 7)) << 4) + (jp & 3) * 4;
        *(uint32_t*)(base + n * 256 + sw)         = pk_bf2(u0, u1);
        *(uint32_t*)(base + (72 + n) * 256 + sw)  = pk_bf2(v0, v1);
    }
}

// ---------------------------------------------------------------------------
// K3: exact binary masks + HMMA + L2 adj prefetch. JSPLIT=4: 256 CTAs =
// single fully-resident wave (was 512 over 296 slots = ragged 2nd wave).
// ---------------------------------------------------------------------------
#define SM_S   0
#define SM_ES  512
#define SM_FS  1024
#define SM_A   2048
#define SM_B   (SM_A + 128 * 512)        // 67584
#define SM_TOT (SM_B + BIMG)             // 104448
#define CPITCH 76

__global__ __launch_bounds__(256, 2) void k_attn(const int* __restrict__ adj) {
    extern __shared__ char smem[];
    float* sS  = (float*)(smem + SM_S);
    float* sES = (float*)(smem + SM_ES);
    float* sFS = (float*)(smem + SM_FS);
    int tid = threadIdx.x, wid = tid >> 5, lane = tid & 31;
    int itile = blockIdx.x & 63, sp = blockIdx.x >> 6;   // sp in 0..3
    int i0 = itile * TILE_I;
    int rb = wid * 16;                 // build rows (all warps build C and D)

    if (tid < 128) {
        sS[tid]  = g_s[i0 + tid];
        sES[tid] = g_es[i0 + tid];
        sFS[tid] = g_fs[i0 + tid];
    }

    int part = wid >> 2;               // 0: C@U, 1: D@V
    int mrb  = (wid & 3) * 32;

    float acc[72];
#pragma unroll
    for (int q = 0; q < 72; ++q) acc[q] = 0.f;

    uint32_t sAu = smem_u32(smem) + SM_A;
    uint32_t sBu = smem_u32(smem) + SM_B;
    uint32_t aRow0 = (uint32_t)mrb + (lane & 15);
    uint32_t aRow1 = aRow0 + 16;
    uint32_t aB0 = sAu + aRow0 * 512;
    uint32_t aB1 = sAu + aRow1 * 512;
    uint32_t cBase = (uint32_t)part * 16 + (uint32_t)(lane >> 4);
    uint32_t bRowL = (uint32_t)(lane & 7);
    uint32_t bHalf = (uint32_t)((lane >> 3) & 1);
    uint32_t bBase = sBu + bRowL * 256 + (uint32_t)part * 72 * 256;

    int j0 = 4 * lane;
    // L2 prefetch addressing: thread t covers row tid>>1, 2 x 128B lines
    const int* pfBase = adj + (size_t)(i0 + (tid >> 1)) * NROWS + (tid & 1) * 64;

    for (int cc = 0; cc < NCHAIN; ++cc) {
        int gch = sp * NCHAIN + cc;
        int jb  = gch * CJ;
        __syncthreads();
        {   // copy prepacked B image (36864 B = 2304 uint4)
            const uint4* src = (const uint4*)(g_UV + (size_t)gch * BIMG);
            uint4* dst = (uint4*)(smem + SM_B);
#pragma unroll
            for (int q = 0; q < 9; ++q) dst[tid + q * 256] = src[tid + q * 256];
        }
        // mask build: 16 rows per warp, 4 j per lane
        float4 dv = *(const float4*)(g_d + jb + j0);
        const int4* ap = (const int4*)(adj + (size_t)(i0 + rb) * NROWS + jb) + lane;
#pragma unroll
        for (int g = 0; g < 4; ++g) {
            int4 a4[4];
#pragma unroll
            for (int r = 0; r < 4; ++r)
                a4[r] = __ldg(ap + (size_t)(g * 4 + r) * (NROWS / 4));
#pragma unroll
            for (int r = 0; r < 4; ++r) {
                uint32_t R  = (uint32_t)rb + g * 4 + r;
                float    sr = sS[R];
                float t0 = sr + dv.x, t1 = sr + dv.y;
                float t2 = sr + dv.z, t3 = sr + dv.w;
                uint32_t h01 = (t0 > 0.f ? 0x3F80u : 0u) | (t1 > 0.f ? 0x3F800000u : 0u);
                uint32_t h23 = (t2 > 0.f ? 0x3F80u : 0u) | (t3 > 0.f ? 0x3F800000u : 0u);
                uint32_t m01 = (uint32_t)a4[r].x * 0xFFFFu + (uint32_t)a4[r].y * 0xFFFF0000u;
                uint32_t m23 = (uint32_t)a4[r].z * 0xFFFFu + (uint32_t)a4[r].w * 0xFFFF0000u;
                uint32_t off = R * 512 + ((((uint32_t)(lane >> 1)) ^ (R & 7)) << 4)
                             + (uint32_t)(lane & 1) * 8;
                *(uint2*)(smem + SM_A + off) = make_uint2(h01 & m01, h23 & m23);
                *(uint2*)(smem + SM_A + off + 256) =
                    make_uint2((h01 ^ 0x3F803F80u) & m01, (h23 ^ 0x3F803F80u) & m23);
            }
        }
        __syncthreads();
        // L2 prefetch of next chunk's adj — streams under the MMA phase
        if (cc < NCHAIN - 1) {
            const int* pf = pfBase + jb + CJ;
            PF_L2(pf);
            PF_L2(pf + 32);
        }

        // HMMA: this warp's part only, 32 rows, 9 n-tiles
#pragma unroll
        for (int ks = 0; ks < 8; ++ks) {
            uint32_t c16 = cBase + 2 * (uint32_t)ks;
            uint32_t A0, A1, A2, A3, A4, A5, A6, A7;
            LDSM4(A0, A1, A2, A3, aB0 + ((c16 ^ (aRow0 & 7)) << 4));
            LDSM4(A4, A5, A6, A7, aB1 + ((c16 ^ (aRow1 & 7)) << 4));
            uint32_t bc16 = 2 * (uint32_t)ks + bHalf;
            uint32_t bA0  = bBase + ((bc16 ^ bRowL) << 4);
#pragma unroll
            for (int nt = 0; nt < 9; ++nt) {
                uint32_t B0, B1;
                LDSM2(B0, B1, bA0 + (uint32_t)nt * 2048);
                MMA16816(acc + nt * 8,     A0, A1, A2, A3, B0, B1);
                MMA16816(acc + nt * 8 + 4, A4, A5, A6, A7, B0, B1);
            }
        }
    }

    // ---- epilogue: stage P/Q to smem, combine Es*P + Fs*Q ----
    __syncthreads();                   // A/B tiles dead; reuse as staging
    float* sC = (float*)(smem + SM_A); // [2][128][CPITCH]
    {
        float* base = sC + (size_t)part * 128 * CPITCH + mrb * CPITCH;
#pragma unroll
        for (int rh = 0; rh < 2; ++rh) {
            int r1 = rh * 16 + (lane >> 2);
            int r2 = r1 + 8;
#pragma unroll
            for (int nt = 0; nt < 9; ++nt) {
                int col = nt * 8 + 2 * (lane & 3);
                *(float2*)(base + r1 * CPITCH + col) =
                    make_float2(acc[nt * 8 + rh * 4 + 0], acc[nt * 8 + rh * 4 + 1]);
                *(float2*)(base + r2 * CPITCH + col) =
                    make_float2(acc[nt * 8 + rh * 4 + 2], acc[nt * 8 + rh * 4 + 3]);
            }
        }
    }
    __syncthreads();
    {
        int row  = tid >> 1, half = tid & 1;
        float es = sES[row], fs = sFS[row];
        const float* pR = sC + row * CPITCH;
        const float* qR = sC + 128 * CPITCH + row * CPITCH;
        float4* o4 = (float4*)(&g_pacc[sp][i0 + row][half * 32]);
#pragma unroll
        for (int n = 0; n < 32; n += 4) {
            int nn = half * 32 + n;
            float4 v;
            v.x = es * pR[nn + 0] + fs * qR[nn + 0];
            v.y = es * pR[nn + 1] + fs * qR[nn + 1];
            v.z = es * pR[nn + 2] + fs * qR[nn + 2];
            v.w = es * pR[nn + 3] + fs * qR[nn + 3];
            o4[n >> 2] = v;
        }
        if (half == 0)
            g_pl[sp][i0 + row] = es * pR[64] + fs * qR[64];
    }
}

// ---------------------------------------------------------------------------
// K4: combine splits, normalize, ELU
// ---------------------------------------------------------------------------
__global__ __launch_bounds__(256) void k_final(float* __restrict__ out) {
    int idx = blockIdx.x * 256 + threadIdx.x;
    int i = idx >> 5, l = idx & 31;
    float a0 = 0.f, a1 = 0.f, ls = 0.f;
#pragma unroll
    for (int sp = 0; sp < JSPLIT; ++sp) {
        float2 p = *(const float2*)(&g_pacc[sp][i][2 * l]);
        a0 += p.x; a1 += p.y;
        ls += g_pl[sp][i];
    }
    float inv = 1.0f / ls;
    a0 *= inv; a1 *= inv;
    a0 = (a0 > 0.f) ? a0 : (fast_exp(a0) - 1.f);
    a1 = (a1 > 0.f) ? a1 : (fast_exp(a1) - 1.f);
    *(float2*)(out + i * 64 + 2 * l) = make_float2(a0, a1);
}

extern "C" void kernel_launch(void* const* d_in, const int* in_sizes, int n_in,
                              void* d_out, int out_size) {
    const float* inp = (const float*)d_in[0];
    const int*   adj = (const int*)d_in[1];
    const float* W   = (const float*)d_in[2];
    const float* a   = (const float*)d_in[3];
    float*       out = (float*)d_out;

    cudaFuncSetAttribute(k_attn, cudaFuncAttributeMaxDynamicSharedMemorySize,
                         SM_TOT);

    k_wh<<<NROWS / 8, 128>>>(inp, W, a);
    k_prep<<<NCHUNKS, 256>>>();
    k_attn<<<64 * JSPLIT, 256, SM_TOT>>>(adj);
    k_final<<<(NROWS * 32) / 256, 256>>>(out);
}